// round 7
// baseline (speedup 1.0000x reference)
#include <cuda_runtime.h>
#include <cuda_bf16.h>
#include <cuda_fp16.h>
#include <math.h>
#include <stdint.h>

#define N_ATOMS 10000
#define N_EDGES 250000
#define F_DIM   128
#define F3      384
#define N_RBF   20
#define CUTOFF  5.0f
#define EPSV    1e-8f
#define NTAB    8192
#define WT_PER_ITER 180224   // 16384+49152+32768+32768+49152

// ---------------- scratch (device globals; no allocation allowed) ----------------
__device__ __half g_tab [(size_t)NTAB * F3];     // fp16 W(d) table (6.3 MB, L2-resident)
__device__ float g_d   [N_EDGES];
__device__ float g_dir [(size_t)N_EDGES * 3];
__device__ float g_q   [N_ATOMS * F_DIM];
__device__ float g_mu  [N_ATOMS * 3 * F_DIM];
__device__ __half g_muh[N_ATOMS * 3 * F_DIM];    // fp16 shadow of mu (gather source)
__device__ __half g_xh [N_ATOMS * F3];           // fp16 shadow of x  (gather source)
__device__ float g_h   [N_ATOMS * F_DIM];
__device__ float g_x   [N_ATOMS * F3];
__device__ float g_dq  [N_ATOMS * F_DIM];
__device__ float g_dmu [N_ATOMS * 3 * F_DIM];
__device__ float g_mumix[N_ATOMS * 3 * 2 * F_DIM];
__device__ float g_ctx [N_ATOMS * 2 * F_DIM];
__device__ float g_hm  [N_ATOMS * F_DIM];
__device__ float g_xm  [N_ATOMS * F3];
__device__ __nv_bfloat16 g_wH[3 * WT_PER_ITER];
__device__ __nv_bfloat16 g_wL[3 * WT_PER_ITER];

__device__ __forceinline__ void split_bf16(float v, __nv_bfloat16& h, __nv_bfloat16& l) {
    h = __float2bfloat16(v);
    l = __float2bfloat16(v - __bfloat162float(h));
}

#define MMA16816(d, a, b) \
    asm volatile("mma.sync.aligned.m16n8k16.row.col.f32.bf16.bf16.f32 " \
        "{%0,%1,%2,%3}, {%4,%5,%6,%7}, {%8,%9}, {%0,%1,%2,%3};" \
        : "+f"((d)[0]), "+f"((d)[1]), "+f"((d)[2]), "+f"((d)[3]) \
        : "r"((a)[0]), "r"((a)[1]), "r"((a)[2]), "r"((a)[3]), \
          "r"((b)[0]), "r"((b)[1]))

// ---------------- fused weight transpose + split for ALL 15 matrices ----------------
__global__ void transpose_all(const float* __restrict__ W1, const float* __restrict__ W2,
                              const float* __restrict__ Wmu, const float* __restrict__ M1,
                              const float* __restrict__ M2) {
    const int Ks[5]  = {128, 128, 128, 256, 128};
    const int Ns[5]  = {128, 384, 256, 128, 384};
    const int off[5] = {0, 16384, 65536, 98304, 131072};
    int m = blockIdx.y;
    int it = m / 5, s = m % 5;
    int K = Ks[s], N = Ns[s];
    int idx = blockIdx.x * blockDim.x + threadIdx.x;
    if (idx >= K * N) return;
    const float* src;
    switch (s) {
        case 0: src = W1  + (size_t)it * 16384; break;
        case 1: src = W2  + (size_t)it * 49152; break;
        case 2: src = Wmu + (size_t)it * 32768; break;
        case 3: src = M1  + (size_t)it * 32768; break;
        default: src = M2 + (size_t)it * 49152; break;
    }
    int k = idx / N, n = idx % N;
    size_t dst = (size_t)it * WT_PER_ITER + off[s] + (size_t)n * K + k;
    __nv_bfloat16 h, l;
    split_bf16(src[idx], h, l);
    g_wH[dst] = h;
    g_wL[dst] = l;
}

// ================= tensor-core GEMM via mma.sync (bf16x3 split) =================
// Optional Ch: fp16 shadow output (same layout as C).
__global__ __launch_bounds__(256)
void mma_gemm(const float* __restrict__ A,
              const __nv_bfloat16* __restrict__ BH,
              const __nv_bfloat16* __restrict__ BL,
              const float* __restrict__ bias, float* __restrict__ C,
              __half* __restrict__ Ch,
              int M, int N, int K, int act) {
    __shared__ __nv_bfloat16 AsH[128][40], AsL[128][40];
    __shared__ __nv_bfloat16 BsH[64][40],  BsL[64][40];

    int tid = threadIdx.x, wid = tid >> 5, lane = tid & 31;
    int row0 = blockIdx.y * 128, col0 = blockIdx.x * 64;
    int wm = wid >> 1, wn = wid & 1;
    int gID = lane >> 2, tig = lane & 3;

    float acc[2][4][4];
    #pragma unroll
    for (int mt = 0; mt < 2; ++mt)
        #pragma unroll
        for (int nt = 0; nt < 4; ++nt)
            #pragma unroll
            for (int i = 0; i < 4; ++i) acc[mt][nt][i] = 0.f;

    for (int k0 = 0; k0 < K; k0 += 32) {
        #pragma unroll
        for (int p = 0; p < 4; ++p) {
            int r = (tid >> 3) + p * 32;
            int c = (tid & 7) * 4;
            int gr = row0 + r;
            float4 v = (gr < M) ? *(const float4*)&A[(size_t)gr * K + k0 + c]
                                : make_float4(0.f, 0.f, 0.f, 0.f);
            __nv_bfloat16 h, l;
            split_bf16(v.x, h, l); AsH[r][c+0] = h; AsL[r][c+0] = l;
            split_bf16(v.y, h, l); AsH[r][c+1] = h; AsL[r][c+1] = l;
            split_bf16(v.z, h, l); AsH[r][c+2] = h; AsL[r][c+2] = l;
            split_bf16(v.w, h, l); AsH[r][c+3] = h; AsL[r][c+3] = l;
        }
        {
            int r = tid >> 2;
            int c = (tid & 3) * 8;
            *(uint4*)&BsH[r][c] = *(const uint4*)&BH[(size_t)(col0 + r) * K + k0 + c];
            *(uint4*)&BsL[r][c] = *(const uint4*)&BL[(size_t)(col0 + r) * K + k0 + c];
        }
        __syncthreads();

        #pragma unroll
        for (int ks = 0; ks < 32; ks += 16) {
            uint32_t ah[2][4], al[2][4], bh[4][2], bl[4][2];
            int cc = ks + tig * 2;
            #pragma unroll
            for (int mt = 0; mt < 2; ++mt) {
                int r = wm * 32 + mt * 16 + gID;
                ah[mt][0] = *(const uint32_t*)&AsH[r][cc];
                ah[mt][1] = *(const uint32_t*)&AsH[r + 8][cc];
                ah[mt][2] = *(const uint32_t*)&AsH[r][cc + 8];
                ah[mt][3] = *(const uint32_t*)&AsH[r + 8][cc + 8];
                al[mt][0] = *(const uint32_t*)&AsL[r][cc];
                al[mt][1] = *(const uint32_t*)&AsL[r + 8][cc];
                al[mt][2] = *(const uint32_t*)&AsL[r][cc + 8];
                al[mt][3] = *(const uint32_t*)&AsL[r + 8][cc + 8];
            }
            #pragma unroll
            for (int nt = 0; nt < 4; ++nt) {
                int cr = wn * 32 + nt * 8 + gID;
                bh[nt][0] = *(const uint32_t*)&BsH[cr][cc];
                bh[nt][1] = *(const uint32_t*)&BsH[cr][cc + 8];
                bl[nt][0] = *(const uint32_t*)&BsL[cr][cc];
                bl[nt][1] = *(const uint32_t*)&BsL[cr][cc + 8];
            }
            #pragma unroll
            for (int mt = 0; mt < 2; ++mt)
                #pragma unroll
                for (int nt = 0; nt < 4; ++nt) {
                    MMA16816(acc[mt][nt], ah[mt], bh[nt]);
                    MMA16816(acc[mt][nt], ah[mt], bl[nt]);
                    MMA16816(acc[mt][nt], al[mt], bh[nt]);
                }
        }
        __syncthreads();
    }

    #pragma unroll
    for (int mt = 0; mt < 2; ++mt) {
        int r = row0 + wm * 32 + mt * 16 + gID;
        #pragma unroll
        for (int nt = 0; nt < 4; ++nt) {
            int c = col0 + wn * 32 + nt * 8 + tig * 2;
            float b0 = bias ? bias[c] : 0.f;
            float b1 = bias ? bias[c + 1] : 0.f;
            float v00 = acc[mt][nt][0] + b0, v01 = acc[mt][nt][1] + b1;
            float v10 = acc[mt][nt][2] + b0, v11 = acc[mt][nt][3] + b1;
            if (act) {
                v00 = v00 / (1.0f + expf(-v00));
                v01 = v01 / (1.0f + expf(-v01));
                v10 = v10 / (1.0f + expf(-v10));
                v11 = v11 / (1.0f + expf(-v11));
            }
            if (r < M) {
                C[(size_t)r * N + c] = v00;
                C[(size_t)r * N + c + 1] = v01;
                if (Ch) {
                    Ch[(size_t)r * N + c] = __float2half(v00);
                    Ch[(size_t)r * N + c + 1] = __float2half(v01);
                }
            }
            if (r + 8 < M) {
                C[(size_t)(r + 8) * N + c] = v10;
                C[(size_t)(r + 8) * N + c + 1] = v11;
                if (Ch) {
                    Ch[(size_t)(r + 8) * N + c] = __float2half(v10);
                    Ch[(size_t)(r + 8) * N + c + 1] = __float2half(v11);
                }
            }
        }
    }
}

// ================= PaiNN pipeline kernels =================
__global__ void edge_geom(const float* __restrict__ R,
                          const int* __restrict__ idx_i,
                          const int* __restrict__ idx_j,
                          const float* __restrict__ offs) {
    int e = blockIdx.x * blockDim.x + threadIdx.x;
    if (e >= N_EDGES) return;
    int i = idx_i[e], j = idx_j[e];
    float rx = R[j*3+0] - R[i*3+0] + offs[e*3+0];
    float ry = R[j*3+1] - R[i*3+1] + offs[e*3+1];
    float rz = R[j*3+2] - R[i*3+2] + offs[e*3+2];
    float d = sqrtf(rx*rx + ry*ry + rz*rz);
    float inv = 1.0f / d;
    g_d[e] = d;
    g_dir[e*3+0] = rx*inv;
    g_dir[e*3+1] = ry*inv;
    g_dir[e*3+2] = rz*inv;
}

__global__ void build_table(const float* __restrict__ filt_W,
                            const float* __restrict__ filt_b) {
    int k = blockIdx.x;
    int c = threadIdx.x;
    __shared__ float s_phi[N_RBF];
    const float step = CUTOFF / (float)(NTAB - 1);
    float d = (float)k * step;
    if (c < N_RBF) {
        const float spacing = CUTOFF / (float)(N_RBF - 1);
        const float coeff = -0.5f / (spacing * spacing);
        float dd = d - (float)c * spacing;
        s_phi[c] = expf(coeff * dd * dd);
    }
    __syncthreads();
    float fc = (d < CUTOFF) ? 0.5f * (cosf(d * (float)(M_PI / 5.0)) + 1.0f) : 0.0f;
    float acc = filt_b[c];
    #pragma unroll
    for (int r = 0; r < N_RBF; ++r)
        acc += s_phi[r] * filt_W[r * F3 + c];
    g_tab[(size_t)k * F3 + c] = __float2half(acc * fc);
}

__global__ void init_atoms(const int* __restrict__ Z, const float* __restrict__ emb) {
    int n = blockIdx.x, t = threadIdx.x;
    int z = Z[n];
    g_q[n * F_DIM + t] = emb[z * F_DIM + t];
    g_dq[n * F_DIM + t] = 0.0f;
    #pragma unroll
    for (int a = 0; a < 3; ++a) {
        g_mu [(n * 3 + a) * F_DIM + t] = 0.0f;
        g_muh[(n * 3 + a) * F_DIM + t] = __float2half(0.0f);
        g_dmu[(n * 3 + a) * F_DIM + t] = 0.0f;
    }
}

#define EPB 50
__global__ void edge_message(const int* __restrict__ idx_i, const int* __restrict__ idx_j) {
    int t = threadIdx.x;
    long e0 = (long)blockIdx.x * EPB;
    long e1 = e0 + EPB; if (e1 > N_EDGES) e1 = N_EDGES;
    int cur = -1;
    float aq = 0.f, a0 = 0.f, a1 = 0.f, a2 = 0.f;
    const float inv_step = (float)(NTAB - 1) / CUTOFF;

    for (long e = e0; e < e1; ++e) {
        int i = idx_i[e];
        if (i != cur) {
            if (cur >= 0) {
                atomicAdd(&g_dq[cur * F_DIM + t], aq);
                atomicAdd(&g_dmu[(cur * 3 + 0) * F_DIM + t], a0);
                atomicAdd(&g_dmu[(cur * 3 + 1) * F_DIM + t], a1);
                atomicAdd(&g_dmu[(cur * 3 + 2) * F_DIM + t], a2);
            }
            cur = i; aq = a0 = a1 = a2 = 0.f;
        }
        float d = g_d[e];
        if (d >= CUTOFF) continue;
        int j = idx_j[e];

        float u = d * inv_step;
        int k = (int)u; if (k > NTAB - 2) k = NTAB - 2;
        float f = u - (float)k;
        const __half* t0 = &g_tab[(size_t)k * F3];
        const __half* t1 = t0 + F3;
        float p00 = __half2float(t0[t]),           p01 = __half2float(t1[t]);
        float p10 = __half2float(t0[F_DIM + t]),   p11 = __half2float(t1[F_DIM + t]);
        float p20 = __half2float(t0[2*F_DIM + t]), p21 = __half2float(t1[2*F_DIM + t]);
        float w0 = fmaf(f, p01 - p00, p00);
        float w1 = fmaf(f, p11 - p10, p10);
        float w2 = fmaf(f, p21 - p20, p20);

        float xj0 = __half2float(g_xh[(long)j * F3 + t]);
        float xj1 = __half2float(g_xh[(long)j * F3 + F_DIM + t]);
        float xj2 = __half2float(g_xh[(long)j * F3 + 2 * F_DIM + t]);
        float m0 = __half2float(g_muh[(j * 3 + 0) * F_DIM + t]);
        float m1 = __half2float(g_muh[(j * 3 + 1) * F_DIM + t]);
        float m2 = __half2float(g_muh[(j * 3 + 2) * F_DIM + t]);
        float d0 = g_dir[e * 3 + 0], d1 = g_dir[e * 3 + 1], d2 = g_dir[e * 3 + 2];

        aq += w0 * xj0;
        float dmuR  = w1 * xj1;
        float dmumu = w2 * xj2;
        a0 += dmuR * d0 + dmumu * m0;
        a1 += dmuR * d1 + dmumu * m1;
        a2 += dmuR * d2 + dmumu * m2;
    }
    if (cur >= 0) {
        atomicAdd(&g_dq[cur * F_DIM + t], aq);
        atomicAdd(&g_dmu[(cur * 3 + 0) * F_DIM + t], a0);
        atomicAdd(&g_dmu[(cur * 3 + 1) * F_DIM + t], a1);
        atomicAdd(&g_dmu[(cur * 3 + 2) * F_DIM + t], a2);
    }
}

__global__ void apply_deltas() {
    int n = blockIdx.x, t = threadIdx.x;
    g_q[n * F_DIM + t] += g_dq[n * F_DIM + t];
    g_dq[n * F_DIM + t] = 0.0f;
    #pragma unroll
    for (int a = 0; a < 3; ++a) {
        g_mu[(n * 3 + a) * F_DIM + t] += g_dmu[(n * 3 + a) * F_DIM + t];
        g_dmu[(n * 3 + a) * F_DIM + t] = 0.0f;
    }
}

__global__ void ctx_kernel() {
    int n = blockIdx.x, t = threadIdx.x;
    float s = EPSV;
    #pragma unroll
    for (int a = 0; a < 3; ++a) {
        float v = g_mumix[(n * 3 + a) * (2 * F_DIM) + t];
        s += v * v;
    }
    g_ctx[n * 2 * F_DIM + t] = g_q[n * F_DIM + t];
    g_ctx[n * 2 * F_DIM + F_DIM + t] = sqrtf(s);
}

__global__ void mix_update() {
    int n = blockIdx.x, t = threadIdx.x;
    float dq   = g_xm[n * F3 + t];
    float dmu  = g_xm[n * F3 + F_DIM + t];
    float dqmu = g_xm[n * F3 + 2 * F_DIM + t];
    float s = 0.f;
    #pragma unroll
    for (int a = 0; a < 3; ++a) {
        float v = g_mumix[(n * 3 + a) * (2 * F_DIM) + t];
        float w = g_mumix[(n * 3 + a) * (2 * F_DIM) + F_DIM + t];
        s += v * w;
        float nm = g_mu[(n * 3 + a) * F_DIM + t] + dmu * w;
        g_mu [(n * 3 + a) * F_DIM + t] = nm;
        g_muh[(n * 3 + a) * F_DIM + t] = __float2half(nm);
    }
    g_q[n * F_DIM + t] += dq + dqmu * s;
}

// ================= host launch =================
extern "C" void kernel_launch(void* const* d_in, const int* in_sizes, int n_in,
                              void* d_out, int out_size) {
    (void)in_sizes; (void)n_in; (void)out_size;
    const int*   Z       = (const int*)  d_in[0];
    const float* R       = (const float*)d_in[1];
    const int*   idx_i   = (const int*)  d_in[2];
    const int*   idx_j   = (const int*)  d_in[3];
    const float* offs    = (const float*)d_in[4];
    const float* emb     = (const float*)d_in[5];
    const float* filt_W  = (const float*)d_in[6];
    const float* filt_b  = (const float*)d_in[7];
    const float* int_W1  = (const float*)d_in[8];
    const float* int_b1  = (const float*)d_in[9];
    const float* int_W2  = (const float*)d_in[10];
    const float* int_b2  = (const float*)d_in[11];
    const float* mix_Wmu = (const float*)d_in[12];
    const float* mix_W1  = (const float*)d_in[13];
    const float* mix_b1  = (const float*)d_in[14];
    const float* mix_W2  = (const float*)d_in[15];
    const float* mix_b2  = (const float*)d_in[16];
    float* out = (float*)d_out;

    void *p_q, *p_mu, *p_h, *p_x, *p_xh, *p_mumix, *p_ctx, *p_hm, *p_xm, *p_wH, *p_wL;
    cudaGetSymbolAddress(&p_q, g_q);
    cudaGetSymbolAddress(&p_mu, g_mu);
    cudaGetSymbolAddress(&p_h, g_h);
    cudaGetSymbolAddress(&p_x, g_x);
    cudaGetSymbolAddress(&p_xh, g_xh);
    cudaGetSymbolAddress(&p_mumix, g_mumix);
    cudaGetSymbolAddress(&p_ctx, g_ctx);
    cudaGetSymbolAddress(&p_hm, g_hm);
    cudaGetSymbolAddress(&p_xm, g_xm);
    cudaGetSymbolAddress(&p_wH, g_wH);
    cudaGetSymbolAddress(&p_wL, g_wL);

    edge_geom<<<(N_EDGES + 255) / 256, 256>>>(R, idx_i, idx_j, offs);
    build_table<<<NTAB, F3>>>(filt_W, filt_b);
    init_atoms<<<N_ATOMS, 128>>>(Z, emb);
    transpose_all<<<dim3(192, 15), 256>>>(int_W1, int_W2, mix_Wmu, mix_W1, mix_W2);

    const __nv_bfloat16* wH = (const __nv_bfloat16*)p_wH;
    const __nv_bfloat16* wL = (const __nv_bfloat16*)p_wL;

    auto gemm = [&](const float* A, size_t woff, const float* bias, float* C,
                    __half* Ch, int M, int N, int K, int act) {
        mma_gemm<<<dim3(N / 64, (M + 127) / 128), 256>>>(
            A, wH + woff, wL + woff, bias, C, Ch, M, N, K, act);
    };

    for (int it = 0; it < 3; ++it) {
        size_t wb = (size_t)it * WT_PER_ITER;
        gemm((const float*)p_q, wb + 0,
             int_b1 + (long)it * F_DIM, (float*)p_h, nullptr, N_ATOMS, F_DIM, F_DIM, 1);
        gemm((const float*)p_h, wb + 16384,
             int_b2 + (long)it * F3, (float*)p_x, (__half*)p_xh, N_ATOMS, F3, F_DIM, 0);

        edge_message<<<(N_EDGES + EPB - 1) / EPB, 128>>>(idx_i, idx_j);
        apply_deltas<<<N_ATOMS, 128>>>();

        gemm((const float*)p_mu, wb + 65536,
             nullptr, (float*)p_mumix, nullptr, 3 * N_ATOMS, 2 * F_DIM, F_DIM, 0);
        ctx_kernel<<<N_ATOMS, 128>>>();
        gemm((const float*)p_ctx, wb + 98304,
             mix_b1 + (long)it * F_DIM, (float*)p_hm, nullptr, N_ATOMS, F_DIM, 2 * F_DIM, 1);
        gemm((const float*)p_hm, wb + 131072,
             mix_b2 + (long)it * F3, (float*)p_xm, nullptr, N_ATOMS, F3, F_DIM, 0);
        mix_update<<<N_ATOMS, 128>>>();
    }

    cudaMemcpyAsync(out, p_q, (size_t)N_ATOMS * F_DIM * sizeof(float),
                    cudaMemcpyDeviceToDevice);
    cudaMemcpyAsync(out + (size_t)N_ATOMS * F_DIM, p_mu,
                    (size_t)N_ATOMS * 3 * F_DIM * sizeof(float),
                    cudaMemcpyDeviceToDevice);
}

// round 8
// speedup vs baseline: 1.1391x; 1.1391x over previous
#include <cuda_runtime.h>
#include <cuda_bf16.h>
#include <cuda_fp16.h>
#include <math.h>
#include <stdint.h>

#define N_ATOMS 10000
#define N_EDGES 250000
#define F_DIM   128
#define F3      384
#define N_RBF   20
#define CUTOFF  5.0f
#define EPSV    1e-8f
#define NTAB    8192
#define WT_PER_ITER 180224   // 16384+49152+32768+32768+49152

// ---------------- scratch (device globals; no allocation allowed) ----------------
__device__ __half g_tab [(size_t)NTAB * F3];     // fp16 W(d) table (6.3 MB, L2-resident)
__device__ float g_d   [N_EDGES];
__device__ float g_dir [(size_t)N_EDGES * 3];
__device__ int   g_row [N_ATOMS + 1];            // CSR row pointers (idx_i is sorted)
__device__ float g_q   [N_ATOMS * F_DIM];
__device__ float g_mu  [N_ATOMS * 3 * F_DIM];
__device__ float g_h   [N_ATOMS * F_DIM];
__device__ float g_x   [N_ATOMS * F3];
__device__ float g_dmu [N_ATOMS * 3 * F_DIM];
__device__ float g_mumix[N_ATOMS * 3 * 2 * F_DIM];
__device__ float g_ctx [N_ATOMS * 2 * F_DIM];
__device__ float g_hm  [N_ATOMS * F_DIM];
__device__ float g_xm  [N_ATOMS * F3];
__device__ __nv_bfloat16 g_wH[3 * WT_PER_ITER];
__device__ __nv_bfloat16 g_wL[3 * WT_PER_ITER];

__device__ __forceinline__ void split_bf16(float v, __nv_bfloat16& h, __nv_bfloat16& l) {
    h = __float2bfloat16(v);
    l = __float2bfloat16(v - __bfloat162float(h));
}

#define MMA16816(d, a, b) \
    asm volatile("mma.sync.aligned.m16n8k16.row.col.f32.bf16.bf16.f32 " \
        "{%0,%1,%2,%3}, {%4,%5,%6,%7}, {%8,%9}, {%0,%1,%2,%3};" \
        : "+f"((d)[0]), "+f"((d)[1]), "+f"((d)[2]), "+f"((d)[3]) \
        : "r"((a)[0]), "r"((a)[1]), "r"((a)[2]), "r"((a)[3]), \
          "r"((b)[0]), "r"((b)[1]))

// ---------------- fused weight transpose + split for ALL 15 matrices ----------------
__global__ void transpose_all(const float* __restrict__ W1, const float* __restrict__ W2,
                              const float* __restrict__ Wmu, const float* __restrict__ M1,
                              const float* __restrict__ M2) {
    const int Ks[5]  = {128, 128, 128, 256, 128};
    const int Ns[5]  = {128, 384, 256, 128, 384};
    const int off[5] = {0, 16384, 65536, 98304, 131072};
    int m = blockIdx.y;
    int it = m / 5, s = m % 5;
    int K = Ks[s], N = Ns[s];
    int idx = blockIdx.x * blockDim.x + threadIdx.x;
    if (idx >= K * N) return;
    const float* src;
    switch (s) {
        case 0: src = W1  + (size_t)it * 16384; break;
        case 1: src = W2  + (size_t)it * 49152; break;
        case 2: src = Wmu + (size_t)it * 32768; break;
        case 3: src = M1  + (size_t)it * 32768; break;
        default: src = M2 + (size_t)it * 49152; break;
    }
    int k = idx / N, n = idx % N;
    size_t dst = (size_t)it * WT_PER_ITER + off[s] + (size_t)n * K + k;
    __nv_bfloat16 h, l;
    split_bf16(src[idx], h, l);
    g_wH[dst] = h;
    g_wL[dst] = l;
}

// ---------------- CSR row pointers: g_row[n] = lower_bound(idx_i, n) ----------------
__global__ void build_rows(const int* __restrict__ idx_i) {
    int n = blockIdx.x * blockDim.x + threadIdx.x;
    if (n > N_ATOMS) return;
    int lo = 0, hi = N_EDGES;
    while (lo < hi) {
        int mid = (lo + hi) >> 1;
        if (idx_i[mid] < n) lo = mid + 1; else hi = mid;
    }
    g_row[n] = lo;
}

// ================= tensor-core GEMM via mma.sync (bf16x3 split) =================
__global__ __launch_bounds__(256)
void mma_gemm(const float* __restrict__ A,
              const __nv_bfloat16* __restrict__ BH,
              const __nv_bfloat16* __restrict__ BL,
              const float* __restrict__ bias, float* __restrict__ C,
              int M, int N, int K, int act) {
    __shared__ __nv_bfloat16 AsH[128][40], AsL[128][40];
    __shared__ __nv_bfloat16 BsH[64][40],  BsL[64][40];

    int tid = threadIdx.x, wid = tid >> 5, lane = tid & 31;
    int row0 = blockIdx.y * 128, col0 = blockIdx.x * 64;
    int wm = wid >> 1, wn = wid & 1;
    int gID = lane >> 2, tig = lane & 3;

    float acc[2][4][4];
    #pragma unroll
    for (int mt = 0; mt < 2; ++mt)
        #pragma unroll
        for (int nt = 0; nt < 4; ++nt)
            #pragma unroll
            for (int i = 0; i < 4; ++i) acc[mt][nt][i] = 0.f;

    for (int k0 = 0; k0 < K; k0 += 32) {
        #pragma unroll
        for (int p = 0; p < 4; ++p) {
            int r = (tid >> 3) + p * 32;
            int c = (tid & 7) * 4;
            int gr = row0 + r;
            float4 v = (gr < M) ? *(const float4*)&A[(size_t)gr * K + k0 + c]
                                : make_float4(0.f, 0.f, 0.f, 0.f);
            __nv_bfloat16 h, l;
            split_bf16(v.x, h, l); AsH[r][c+0] = h; AsL[r][c+0] = l;
            split_bf16(v.y, h, l); AsH[r][c+1] = h; AsL[r][c+1] = l;
            split_bf16(v.z, h, l); AsH[r][c+2] = h; AsL[r][c+2] = l;
            split_bf16(v.w, h, l); AsH[r][c+3] = h; AsL[r][c+3] = l;
        }
        {
            int r = tid >> 2;
            int c = (tid & 3) * 8;
            *(uint4*)&BsH[r][c] = *(const uint4*)&BH[(size_t)(col0 + r) * K + k0 + c];
            *(uint4*)&BsL[r][c] = *(const uint4*)&BL[(size_t)(col0 + r) * K + k0 + c];
        }
        __syncthreads();

        #pragma unroll
        for (int ks = 0; ks < 32; ks += 16) {
            uint32_t ah[2][4], al[2][4], bh[4][2], bl[4][2];
            int cc = ks + tig * 2;
            #pragma unroll
            for (int mt = 0; mt < 2; ++mt) {
                int r = wm * 32 + mt * 16 + gID;
                ah[mt][0] = *(const uint32_t*)&AsH[r][cc];
                ah[mt][1] = *(const uint32_t*)&AsH[r + 8][cc];
                ah[mt][2] = *(const uint32_t*)&AsH[r][cc + 8];
                ah[mt][3] = *(const uint32_t*)&AsH[r + 8][cc + 8];
                al[mt][0] = *(const uint32_t*)&AsL[r][cc];
                al[mt][1] = *(const uint32_t*)&AsL[r + 8][cc];
                al[mt][2] = *(const uint32_t*)&AsL[r][cc + 8];
                al[mt][3] = *(const uint32_t*)&AsL[r + 8][cc + 8];
            }
            #pragma unroll
            for (int nt = 0; nt < 4; ++nt) {
                int cr = wn * 32 + nt * 8 + gID;
                bh[nt][0] = *(const uint32_t*)&BsH[cr][cc];
                bh[nt][1] = *(const uint32_t*)&BsH[cr][cc + 8];
                bl[nt][0] = *(const uint32_t*)&BsL[cr][cc];
                bl[nt][1] = *(const uint32_t*)&BsL[cr][cc + 8];
            }
            #pragma unroll
            for (int mt = 0; mt < 2; ++mt)
                #pragma unroll
                for (int nt = 0; nt < 4; ++nt) {
                    MMA16816(acc[mt][nt], ah[mt], bh[nt]);
                    MMA16816(acc[mt][nt], ah[mt], bl[nt]);
                    MMA16816(acc[mt][nt], al[mt], bh[nt]);
                }
        }
        __syncthreads();
    }

    #pragma unroll
    for (int mt = 0; mt < 2; ++mt) {
        int r = row0 + wm * 32 + mt * 16 + gID;
        #pragma unroll
        for (int nt = 0; nt < 4; ++nt) {
            int c = col0 + wn * 32 + nt * 8 + tig * 2;
            float b0 = bias ? bias[c] : 0.f;
            float b1 = bias ? bias[c + 1] : 0.f;
            float v00 = acc[mt][nt][0] + b0, v01 = acc[mt][nt][1] + b1;
            float v10 = acc[mt][nt][2] + b0, v11 = acc[mt][nt][3] + b1;
            if (act) {
                v00 = v00 / (1.0f + expf(-v00));
                v01 = v01 / (1.0f + expf(-v01));
                v10 = v10 / (1.0f + expf(-v10));
                v11 = v11 / (1.0f + expf(-v11));
            }
            if (r < M)     { C[(size_t)r * N + c] = v00;       C[(size_t)r * N + c + 1] = v01; }
            if (r + 8 < M) { C[(size_t)(r + 8) * N + c] = v10; C[(size_t)(r + 8) * N + c + 1] = v11; }
        }
    }
}

// ================= PaiNN pipeline kernels =================
__global__ void edge_geom(const float* __restrict__ R,
                          const int* __restrict__ idx_i,
                          const int* __restrict__ idx_j,
                          const float* __restrict__ offs) {
    int e = blockIdx.x * blockDim.x + threadIdx.x;
    if (e >= N_EDGES) return;
    int i = idx_i[e], j = idx_j[e];
    float rx = R[j*3+0] - R[i*3+0] + offs[e*3+0];
    float ry = R[j*3+1] - R[i*3+1] + offs[e*3+1];
    float rz = R[j*3+2] - R[i*3+2] + offs[e*3+2];
    float d = sqrtf(rx*rx + ry*ry + rz*rz);
    float inv = 1.0f / d;
    g_d[e] = d;
    g_dir[e*3+0] = rx*inv;
    g_dir[e*3+1] = ry*inv;
    g_dir[e*3+2] = rz*inv;
}

__global__ void build_table(const float* __restrict__ filt_W,
                            const float* __restrict__ filt_b) {
    int k = blockIdx.x;
    int c = threadIdx.x;
    __shared__ float s_phi[N_RBF];
    const float step = CUTOFF / (float)(NTAB - 1);
    float d = (float)k * step;
    if (c < N_RBF) {
        const float spacing = CUTOFF / (float)(N_RBF - 1);
        const float coeff = -0.5f / (spacing * spacing);
        float dd = d - (float)c * spacing;
        s_phi[c] = expf(coeff * dd * dd);
    }
    __syncthreads();
    float fc = (d < CUTOFF) ? 0.5f * (cosf(d * (float)(M_PI / 5.0)) + 1.0f) : 0.0f;
    float acc = filt_b[c];
    #pragma unroll
    for (int r = 0; r < N_RBF; ++r)
        acc += s_phi[r] * filt_W[r * F3 + c];
    g_tab[(size_t)k * F3 + c] = __float2half(acc * fc);
}

__global__ void init_atoms(const int* __restrict__ Z, const float* __restrict__ emb) {
    int n = blockIdx.x, t = threadIdx.x;
    int z = Z[n];
    g_q[n * F_DIM + t] = emb[z * F_DIM + t];
    #pragma unroll
    for (int a = 0; a < 3; ++a)
        g_mu[(n * 3 + a) * F_DIM + t] = 0.0f;
}

// ---------------- CSR edge message pass: one block per atom, no atomics ----------------
__global__ void edge_message_csr(const int* __restrict__ idx_j) {
    int n = blockIdx.x, t = threadIdx.x;   // 128 threads = F_DIM
    int e0 = g_row[n], e1 = g_row[n + 1];
    float aq = 0.f, a0 = 0.f, a1 = 0.f, a2 = 0.f;
    const float inv_step = (float)(NTAB - 1) / CUTOFF;

    for (int e = e0; e < e1; ++e) {
        float d = g_d[e];
        if (d >= CUTOFF) continue;
        int j = idx_j[e];

        float u = d * inv_step;
        int k = (int)u; if (k > NTAB - 2) k = NTAB - 2;
        float f = u - (float)k;
        const __half* t0 = &g_tab[(size_t)k * F3];
        const __half* t1 = t0 + F3;
        float p00 = __half2float(t0[t]),           p01 = __half2float(t1[t]);
        float p10 = __half2float(t0[F_DIM + t]),   p11 = __half2float(t1[F_DIM + t]);
        float p20 = __half2float(t0[2*F_DIM + t]), p21 = __half2float(t1[2*F_DIM + t]);
        float w0 = fmaf(f, p01 - p00, p00);
        float w1 = fmaf(f, p11 - p10, p10);
        float w2 = fmaf(f, p21 - p20, p20);

        float xj0 = g_x[(long)j * F3 + t];
        float xj1 = g_x[(long)j * F3 + F_DIM + t];
        float xj2 = g_x[(long)j * F3 + 2 * F_DIM + t];
        float m0 = g_mu[(j * 3 + 0) * F_DIM + t];
        float m1 = g_mu[(j * 3 + 1) * F_DIM + t];
        float m2 = g_mu[(j * 3 + 2) * F_DIM + t];
        float d0 = g_dir[e * 3 + 0], d1 = g_dir[e * 3 + 1], d2 = g_dir[e * 3 + 2];

        aq += w0 * xj0;
        float dmuR  = w1 * xj1;
        float dmumu = w2 * xj2;
        a0 += dmuR * d0 + dmumu * m0;
        a1 += dmuR * d1 + dmumu * m1;
        a2 += dmuR * d2 + dmumu * m2;
    }
    // q is never gathered in this kernel -> safe to fuse the update.
    g_q[n * F_DIM + t] += aq;
    // mu IS gathered (mu[j]) -> stage dmu, apply after kernel. Plain overwrite (no zeroing).
    g_dmu[(n * 3 + 0) * F_DIM + t] = a0;
    g_dmu[(n * 3 + 1) * F_DIM + t] = a1;
    g_dmu[(n * 3 + 2) * F_DIM + t] = a2;
}

__global__ void apply_mu() {
    int n = blockIdx.x, t = threadIdx.x;
    #pragma unroll
    for (int a = 0; a < 3; ++a)
        g_mu[(n * 3 + a) * F_DIM + t] += g_dmu[(n * 3 + a) * F_DIM + t];
}

__global__ void ctx_kernel() {
    int n = blockIdx.x, t = threadIdx.x;
    float s = EPSV;
    #pragma unroll
    for (int a = 0; a < 3; ++a) {
        float v = g_mumix[(n * 3 + a) * (2 * F_DIM) + t];
        s += v * v;
    }
    g_ctx[n * 2 * F_DIM + t] = g_q[n * F_DIM + t];
    g_ctx[n * 2 * F_DIM + F_DIM + t] = sqrtf(s);
}

__global__ void mix_update() {
    int n = blockIdx.x, t = threadIdx.x;
    float dq   = g_xm[n * F3 + t];
    float dmu  = g_xm[n * F3 + F_DIM + t];
    float dqmu = g_xm[n * F3 + 2 * F_DIM + t];
    float s = 0.f;
    #pragma unroll
    for (int a = 0; a < 3; ++a) {
        float v = g_mumix[(n * 3 + a) * (2 * F_DIM) + t];
        float w = g_mumix[(n * 3 + a) * (2 * F_DIM) + F_DIM + t];
        s += v * w;
        g_mu[(n * 3 + a) * F_DIM + t] += dmu * w;
    }
    g_q[n * F_DIM + t] += dq + dqmu * s;
}

// ================= host launch =================
extern "C" void kernel_launch(void* const* d_in, const int* in_sizes, int n_in,
                              void* d_out, int out_size) {
    (void)in_sizes; (void)n_in; (void)out_size;
    const int*   Z       = (const int*)  d_in[0];
    const float* R       = (const float*)d_in[1];
    const int*   idx_i   = (const int*)  d_in[2];
    const int*   idx_j   = (const int*)  d_in[3];
    const float* offs    = (const float*)d_in[4];
    const float* emb     = (const float*)d_in[5];
    const float* filt_W  = (const float*)d_in[6];
    const float* filt_b  = (const float*)d_in[7];
    const float* int_W1  = (const float*)d_in[8];
    const float* int_b1  = (const float*)d_in[9];
    const float* int_W2  = (const float*)d_in[10];
    const float* int_b2  = (const float*)d_in[11];
    const float* mix_Wmu = (const float*)d_in[12];
    const float* mix_W1  = (const float*)d_in[13];
    const float* mix_b1  = (const float*)d_in[14];
    const float* mix_W2  = (const float*)d_in[15];
    const float* mix_b2  = (const float*)d_in[16];
    float* out = (float*)d_out;

    void *p_q, *p_mu, *p_h, *p_x, *p_mumix, *p_ctx, *p_hm, *p_xm, *p_wH, *p_wL;
    cudaGetSymbolAddress(&p_q, g_q);
    cudaGetSymbolAddress(&p_mu, g_mu);
    cudaGetSymbolAddress(&p_h, g_h);
    cudaGetSymbolAddress(&p_x, g_x);
    cudaGetSymbolAddress(&p_mumix, g_mumix);
    cudaGetSymbolAddress(&p_ctx, g_ctx);
    cudaGetSymbolAddress(&p_hm, g_hm);
    cudaGetSymbolAddress(&p_xm, g_xm);
    cudaGetSymbolAddress(&p_wH, g_wH);
    cudaGetSymbolAddress(&p_wL, g_wL);

    edge_geom<<<(N_EDGES + 255) / 256, 256>>>(R, idx_i, idx_j, offs);
    build_table<<<NTAB, F3>>>(filt_W, filt_b);
    init_atoms<<<N_ATOMS, 128>>>(Z, emb);
    transpose_all<<<dim3(192, 15), 256>>>(int_W1, int_W2, mix_Wmu, mix_W1, mix_W2);
    build_rows<<<(N_ATOMS + 256) / 256, 256>>>(idx_i);

    const __nv_bfloat16* wH = (const __nv_bfloat16*)p_wH;
    const __nv_bfloat16* wL = (const __nv_bfloat16*)p_wL;

    auto gemm = [&](const float* A, size_t woff, const float* bias, float* C,
                    int M, int N, int K, int act) {
        mma_gemm<<<dim3(N / 64, (M + 127) / 128), 256>>>(
            A, wH + woff, wL + woff, bias, C, M, N, K, act);
    };

    for (int it = 0; it < 3; ++it) {
        size_t wb = (size_t)it * WT_PER_ITER;
        gemm((const float*)p_q, wb + 0,
             int_b1 + (long)it * F_DIM, (float*)p_h, N_ATOMS, F_DIM, F_DIM, 1);
        gemm((const float*)p_h, wb + 16384,
             int_b2 + (long)it * F3, (float*)p_x, N_ATOMS, F3, F_DIM, 0);

        edge_message_csr<<<N_ATOMS, 128>>>(idx_j);
        apply_mu<<<N_ATOMS, 128>>>();

        gemm((const float*)p_mu, wb + 65536,
             nullptr, (float*)p_mumix, 3 * N_ATOMS, 2 * F_DIM, F_DIM, 0);
        ctx_kernel<<<N_ATOMS, 128>>>();
        gemm((const float*)p_ctx, wb + 98304,
             mix_b1 + (long)it * F_DIM, (float*)p_hm, N_ATOMS, F_DIM, 2 * F_DIM, 1);
        gemm((const float*)p_hm, wb + 131072,
             mix_b2 + (long)it * F3, (float*)p_xm, N_ATOMS, F3, F_DIM, 0);
        mix_update<<<N_ATOMS, 128>>>();
    }

    cudaMemcpyAsync(out, p_q, (size_t)N_ATOMS * F_DIM * sizeof(float),
                    cudaMemcpyDeviceToDevice);
    cudaMemcpyAsync(out + (size_t)N_ATOMS * F_DIM, p_mu,
                    (size_t)N_ATOMS * 3 * F_DIM * sizeof(float),
                    cudaMemcpyDeviceToDevice);
}

// round 9
// speedup vs baseline: 1.1604x; 1.0187x over previous
#include <cuda_runtime.h>
#include <cuda_bf16.h>
#include <cuda_fp16.h>
#include <math.h>
#include <stdint.h>

#define N_ATOMS 10000
#define N_EDGES 250000
#define F_DIM   128
#define F3      384
#define N_RBF   20
#define CUTOFF  5.0f
#define EPSV    1e-8f
#define NTAB    8192
#define INV_STEP ((float)(NTAB - 1) / CUTOFF)
#define WT_PER_ITER 180224   // 16384+49152+32768+32768+49152

// ---------------- scratch (device globals; no allocation allowed) ----------------
__device__ __half2 g_tab2[(size_t)NTAB * F3];    // interleaved (W_k, W_{k+1}) lerp table
__device__ float4 g_geo [N_EDGES];               // (dir.x, dir.y, dir.z, d)
__device__ int    g_row [N_ATOMS + 1];           // CSR row pointers (idx_i is sorted)
__device__ float g_q   [N_ATOMS * F_DIM];
__device__ float g_mu  [N_ATOMS * 3 * F_DIM];
__device__ float g_h   [N_ATOMS * F_DIM];
__device__ float g_x   [N_ATOMS * F3];
__device__ float g_dmu [N_ATOMS * 3 * F_DIM];
__device__ float g_mumix[N_ATOMS * 3 * 2 * F_DIM];
__device__ float g_ctx [N_ATOMS * 2 * F_DIM];
__device__ float g_hm  [N_ATOMS * F_DIM];
__device__ float g_xm  [N_ATOMS * F3];
__device__ __nv_bfloat16 g_wH[3 * WT_PER_ITER];
__device__ __nv_bfloat16 g_wL[3 * WT_PER_ITER];

__device__ __forceinline__ void split_bf16(float v, __nv_bfloat16& h, __nv_bfloat16& l) {
    h = __float2bfloat16(v);
    l = __float2bfloat16(v - __bfloat162float(h));
}

#define MMA16816(d, a, b) \
    asm volatile("mma.sync.aligned.m16n8k16.row.col.f32.bf16.bf16.f32 " \
        "{%0,%1,%2,%3}, {%4,%5,%6,%7}, {%8,%9}, {%0,%1,%2,%3};" \
        : "+f"((d)[0]), "+f"((d)[1]), "+f"((d)[2]), "+f"((d)[3]) \
        : "r"((a)[0]), "r"((a)[1]), "r"((a)[2]), "r"((a)[3]), \
          "r"((b)[0]), "r"((b)[1]))

// ---------------- fused weight transpose + split for ALL 15 matrices ----------------
__global__ void transpose_all(const float* __restrict__ W1, const float* __restrict__ W2,
                              const float* __restrict__ Wmu, const float* __restrict__ M1,
                              const float* __restrict__ M2) {
    const int Ks[5]  = {128, 128, 128, 256, 128};
    const int Ns[5]  = {128, 384, 256, 128, 384};
    const int off[5] = {0, 16384, 65536, 98304, 131072};
    int m = blockIdx.y;
    int it = m / 5, s = m % 5;
    int K = Ks[s], N = Ns[s];
    int idx = blockIdx.x * blockDim.x + threadIdx.x;
    if (idx >= K * N) return;
    const float* src;
    switch (s) {
        case 0: src = W1  + (size_t)it * 16384; break;
        case 1: src = W2  + (size_t)it * 49152; break;
        case 2: src = Wmu + (size_t)it * 32768; break;
        case 3: src = M1  + (size_t)it * 32768; break;
        default: src = M2 + (size_t)it * 49152; break;
    }
    int k = idx / N, n = idx % N;
    size_t dst = (size_t)it * WT_PER_ITER + off[s] + (size_t)n * K + k;
    __nv_bfloat16 h, l;
    split_bf16(src[idx], h, l);
    g_wH[dst] = h;
    g_wL[dst] = l;
}

// ---------------- CSR row pointers ----------------
__global__ void build_rows(const int* __restrict__ idx_i) {
    int n = blockIdx.x * blockDim.x + threadIdx.x;
    if (n > N_ATOMS) return;
    int lo = 0, hi = N_EDGES;
    while (lo < hi) {
        int mid = (lo + hi) >> 1;
        if (idx_i[mid] < n) lo = mid + 1; else hi = mid;
    }
    g_row[n] = lo;
}

// ================= tensor-core GEMM via mma.sync (bf16x3 split) =================
// k-loop with register prefetch of next chunk's global loads (hidden behind MMA).
__global__ __launch_bounds__(256)
void mma_gemm(const float* __restrict__ A,
              const __nv_bfloat16* __restrict__ BH,
              const __nv_bfloat16* __restrict__ BL,
              const float* __restrict__ bias, float* __restrict__ C,
              int M, int N, int K, int act) {
    __shared__ __nv_bfloat16 AsH[128][40], AsL[128][40];
    __shared__ __nv_bfloat16 BsH[64][40],  BsL[64][40];

    int tid = threadIdx.x, wid = tid >> 5, lane = tid & 31;
    int row0 = blockIdx.y * 128, col0 = blockIdx.x * 64;
    int wm = wid >> 1, wn = wid & 1;
    int gID = lane >> 2, tig = lane & 3;

    float acc[2][4][4];
    #pragma unroll
    for (int mt = 0; mt < 2; ++mt)
        #pragma unroll
        for (int nt = 0; nt < 4; ++nt)
            #pragma unroll
            for (int i = 0; i < 4; ++i) acc[mt][nt][i] = 0.f;

    int nc = K >> 5;
    float4 ra[4];
    uint4 rbh, rbl;
    int br = tid >> 2, bc = (tid & 3) * 8;

    // prologue loads (chunk 0)
    #pragma unroll
    for (int p = 0; p < 4; ++p) {
        int r = (tid >> 3) + p * 32, cc = (tid & 7) * 4, gr = row0 + r;
        ra[p] = (gr < M) ? *(const float4*)&A[(size_t)gr * K + cc]
                         : make_float4(0.f, 0.f, 0.f, 0.f);
    }
    rbh = *(const uint4*)&BH[(size_t)(col0 + br) * K + bc];
    rbl = *(const uint4*)&BL[(size_t)(col0 + br) * K + bc];

    for (int c = 0; c < nc; ++c) {
        // stage regs -> smem with bf16 split
        #pragma unroll
        for (int p = 0; p < 4; ++p) {
            int r = (tid >> 3) + p * 32, cc = (tid & 7) * 4;
            __nv_bfloat16 h, l;
            split_bf16(ra[p].x, h, l); AsH[r][cc+0] = h; AsL[r][cc+0] = l;
            split_bf16(ra[p].y, h, l); AsH[r][cc+1] = h; AsL[r][cc+1] = l;
            split_bf16(ra[p].z, h, l); AsH[r][cc+2] = h; AsL[r][cc+2] = l;
            split_bf16(ra[p].w, h, l); AsH[r][cc+3] = h; AsL[r][cc+3] = l;
        }
        *(uint4*)&BsH[br][bc] = rbh;
        *(uint4*)&BsL[br][bc] = rbl;
        __syncthreads();

        // prefetch next chunk (overlaps the MMA section below)
        if (c + 1 < nc) {
            int k0n = (c + 1) << 5;
            #pragma unroll
            for (int p = 0; p < 4; ++p) {
                int r = (tid >> 3) + p * 32, cc = (tid & 7) * 4, gr = row0 + r;
                ra[p] = (gr < M) ? *(const float4*)&A[(size_t)gr * K + k0n + cc]
                                 : make_float4(0.f, 0.f, 0.f, 0.f);
            }
            rbh = *(const uint4*)&BH[(size_t)(col0 + br) * K + k0n + bc];
            rbl = *(const uint4*)&BL[(size_t)(col0 + br) * K + k0n + bc];
        }

        #pragma unroll
        for (int ks = 0; ks < 32; ks += 16) {
            uint32_t ah[2][4], al[2][4], bh[4][2], bl[4][2];
            int cc = ks + tig * 2;
            #pragma unroll
            for (int mt = 0; mt < 2; ++mt) {
                int r = wm * 32 + mt * 16 + gID;
                ah[mt][0] = *(const uint32_t*)&AsH[r][cc];
                ah[mt][1] = *(const uint32_t*)&AsH[r + 8][cc];
                ah[mt][2] = *(const uint32_t*)&AsH[r][cc + 8];
                ah[mt][3] = *(const uint32_t*)&AsH[r + 8][cc + 8];
                al[mt][0] = *(const uint32_t*)&AsL[r][cc];
                al[mt][1] = *(const uint32_t*)&AsL[r + 8][cc];
                al[mt][2] = *(const uint32_t*)&AsL[r][cc + 8];
                al[mt][3] = *(const uint32_t*)&AsL[r + 8][cc + 8];
            }
            #pragma unroll
            for (int nt = 0; nt < 4; ++nt) {
                int cr = wn * 32 + nt * 8 + gID;
                bh[nt][0] = *(const uint32_t*)&BsH[cr][cc];
                bh[nt][1] = *(const uint32_t*)&BsH[cr][cc + 8];
                bl[nt][0] = *(const uint32_t*)&BsL[cr][cc];
                bl[nt][1] = *(const uint32_t*)&BsL[cr][cc + 8];
            }
            #pragma unroll
            for (int mt = 0; mt < 2; ++mt)
                #pragma unroll
                for (int nt = 0; nt < 4; ++nt) {
                    MMA16816(acc[mt][nt], ah[mt], bh[nt]);
                    MMA16816(acc[mt][nt], ah[mt], bl[nt]);
                    MMA16816(acc[mt][nt], al[mt], bh[nt]);
                }
        }
        __syncthreads();
    }

    #pragma unroll
    for (int mt = 0; mt < 2; ++mt) {
        int r = row0 + wm * 32 + mt * 16 + gID;
        #pragma unroll
        for (int nt = 0; nt < 4; ++nt) {
            int c = col0 + wn * 32 + nt * 8 + tig * 2;
            float b0 = bias ? bias[c] : 0.f;
            float b1 = bias ? bias[c + 1] : 0.f;
            float v00 = acc[mt][nt][0] + b0, v01 = acc[mt][nt][1] + b1;
            float v10 = acc[mt][nt][2] + b0, v11 = acc[mt][nt][3] + b1;
            if (act) {
                v00 = v00 / (1.0f + expf(-v00));
                v01 = v01 / (1.0f + expf(-v01));
                v10 = v10 / (1.0f + expf(-v10));
                v11 = v11 / (1.0f + expf(-v11));
            }
            if (r < M)     { C[(size_t)r * N + c] = v00;       C[(size_t)r * N + c + 1] = v01; }
            if (r + 8 < M) { C[(size_t)(r + 8) * N + c] = v10; C[(size_t)(r + 8) * N + c + 1] = v11; }
        }
    }
}

// ================= PaiNN pipeline kernels =================
__global__ void edge_geom(const float* __restrict__ R,
                          const int* __restrict__ idx_i,
                          const int* __restrict__ idx_j,
                          const float* __restrict__ offs) {
    int e = blockIdx.x * blockDim.x + threadIdx.x;
    if (e >= N_EDGES) return;
    int i = idx_i[e], j = idx_j[e];
    float rx = R[j*3+0] - R[i*3+0] + offs[e*3+0];
    float ry = R[j*3+1] - R[i*3+1] + offs[e*3+1];
    float rz = R[j*3+2] - R[i*3+2] + offs[e*3+2];
    float d = sqrtf(rx*rx + ry*ry + rz*rz);
    float inv = 1.0f / d;
    g_geo[e] = make_float4(rx*inv, ry*inv, rz*inv, d);
}

// interleaved table: entry (k, c) = (W_k[c], W_{k+1}[c]) as half2
__global__ void build_table(const float* __restrict__ filt_W,
                            const float* __restrict__ filt_b) {
    int k = blockIdx.x;
    int c = threadIdx.x;
    __shared__ float s_phi[2][N_RBF];
    const float step = CUTOFF / (float)(NTAB - 1);
    float d0 = (float)k * step;
    int k1 = (k + 1 < NTAB) ? k + 1 : k;
    float d1 = (float)k1 * step;
    if (c < N_RBF) {
        const float spacing = CUTOFF / (float)(N_RBF - 1);
        const float coeff = -0.5f / (spacing * spacing);
        float dd0 = d0 - (float)c * spacing;
        float dd1 = d1 - (float)c * spacing;
        s_phi[0][c] = expf(coeff * dd0 * dd0);
        s_phi[1][c] = expf(coeff * dd1 * dd1);
    }
    __syncthreads();
    float fc0 = (d0 < CUTOFF) ? 0.5f * (cosf(d0 * (float)(M_PI / 5.0)) + 1.0f) : 0.0f;
    float fc1 = (d1 < CUTOFF) ? 0.5f * (cosf(d1 * (float)(M_PI / 5.0)) + 1.0f) : 0.0f;
    float a0 = filt_b[c], a1 = filt_b[c];
    #pragma unroll
    for (int r = 0; r < N_RBF; ++r) {
        float w = filt_W[r * F3 + c];
        a0 += s_phi[0][r] * w;
        a1 += s_phi[1][r] * w;
    }
    g_tab2[(size_t)k * F3 + c] = __floats2half2_rn(a0 * fc0, a1 * fc1);
}

__global__ void init_atoms(const int* __restrict__ Z, const float* __restrict__ emb) {
    int n = blockIdx.x, t = threadIdx.x;
    int z = Z[n];
    g_q[n * F_DIM + t] = emb[z * F_DIM + t];
    #pragma unroll
    for (int a = 0; a < 3; ++a)
        g_mu[(n * 3 + a) * F_DIM + t] = 0.0f;
}

// ---------------- per-edge contribution (inlined) ----------------
__device__ __forceinline__ void edge_body(const int* __restrict__ idx_j, int e, int t,
                                          float& aq, float& a0, float& a1, float& a2) {
    float4 g = g_geo[e];
    float d = g.w;
    if (d >= CUTOFF) return;       // block-uniform branch
    int j = idx_j[e];

    float u = d * INV_STEP;
    int k = (int)u; if (k > NTAB - 2) k = NTAB - 2;
    float f = u - (float)k;
    const __half2* tp = &g_tab2[(size_t)k * F3];
    float2 p0 = __half22float2(tp[t]);
    float2 p1 = __half22float2(tp[F_DIM + t]);
    float2 p2 = __half22float2(tp[2 * F_DIM + t]);
    float w0 = fmaf(f, p0.y - p0.x, p0.x);
    float w1 = fmaf(f, p1.y - p1.x, p1.x);
    float w2 = fmaf(f, p2.y - p2.x, p2.x);

    const float* xr = &g_x[(size_t)j * F3];
    float xj0 = xr[t], xj1 = xr[F_DIM + t], xj2 = xr[2 * F_DIM + t];
    const float* mr = &g_mu[(size_t)j * 3 * F_DIM];
    float m0 = mr[t], m1 = mr[F_DIM + t], m2 = mr[2 * F_DIM + t];

    aq += w0 * xj0;
    float dmuR  = w1 * xj1;
    float dmumu = w2 * xj2;
    a0 += dmuR * g.x + dmumu * m0;
    a1 += dmuR * g.y + dmumu * m1;
    a2 += dmuR * g.z + dmumu * m2;
}

// ---------------- CSR edge message pass: one block per atom, unroll-2 ----------------
__global__ void edge_message_csr(const int* __restrict__ idx_j) {
    int n = blockIdx.x, t = threadIdx.x;   // 128 threads = F_DIM
    int e0 = g_row[n], e1 = g_row[n + 1];
    float aq0 = 0.f, x0 = 0.f, y0 = 0.f, z0 = 0.f;
    float aq1 = 0.f, x1 = 0.f, y1 = 0.f, z1 = 0.f;

    int e = e0;
    for (; e + 2 <= e1; e += 2) {
        edge_body(idx_j, e,     t, aq0, x0, y0, z0);
        edge_body(idx_j, e + 1, t, aq1, x1, y1, z1);
    }
    if (e < e1) edge_body(idx_j, e, t, aq0, x0, y0, z0);

    g_q[n * F_DIM + t] += aq0 + aq1;
    g_dmu[(n * 3 + 0) * F_DIM + t] = x0 + x1;
    g_dmu[(n * 3 + 1) * F_DIM + t] = y0 + y1;
    g_dmu[(n * 3 + 2) * F_DIM + t] = z0 + z1;
}

__global__ void apply_mu() {
    int n = blockIdx.x, t = threadIdx.x;
    #pragma unroll
    for (int a = 0; a < 3; ++a)
        g_mu[(n * 3 + a) * F_DIM + t] += g_dmu[(n * 3 + a) * F_DIM + t];
}

__global__ void ctx_kernel() {
    int n = blockIdx.x, t = threadIdx.x;
    float s = EPSV;
    #pragma unroll
    for (int a = 0; a < 3; ++a) {
        float v = g_mumix[(n * 3 + a) * (2 * F_DIM) + t];
        s += v * v;
    }
    g_ctx[n * 2 * F_DIM + t] = g_q[n * F_DIM + t];
    g_ctx[n * 2 * F_DIM + F_DIM + t] = sqrtf(s);
}

__global__ void mix_update() {
    int n = blockIdx.x, t = threadIdx.x;
    float dq   = g_xm[n * F3 + t];
    float dmu  = g_xm[n * F3 + F_DIM + t];
    float dqmu = g_xm[n * F3 + 2 * F_DIM + t];
    float s = 0.f;
    #pragma unroll
    for (int a = 0; a < 3; ++a) {
        float v = g_mumix[(n * 3 + a) * (2 * F_DIM) + t];
        float w = g_mumix[(n * 3 + a) * (2 * F_DIM) + F_DIM + t];
        s += v * w;
        g_mu[(n * 3 + a) * F_DIM + t] += dmu * w;
    }
    g_q[n * F_DIM + t] += dq + dqmu * s;
}

// ================= host launch =================
extern "C" void kernel_launch(void* const* d_in, const int* in_sizes, int n_in,
                              void* d_out, int out_size) {
    (void)in_sizes; (void)n_in; (void)out_size;
    const int*   Z       = (const int*)  d_in[0];
    const float* R       = (const float*)d_in[1];
    const int*   idx_i   = (const int*)  d_in[2];
    const int*   idx_j   = (const int*)  d_in[3];
    const float* offs    = (const float*)d_in[4];
    const float* emb     = (const float*)d_in[5];
    const float* filt_W  = (const float*)d_in[6];
    const float* filt_b  = (const float*)d_in[7];
    const float* int_W1  = (const float*)d_in[8];
    const float* int_b1  = (const float*)d_in[9];
    const float* int_W2  = (const float*)d_in[10];
    const float* int_b2  = (const float*)d_in[11];
    const float* mix_Wmu = (const float*)d_in[12];
    const float* mix_W1  = (const float*)d_in[13];
    const float* mix_b1  = (const float*)d_in[14];
    const float* mix_W2  = (const float*)d_in[15];
    const float* mix_b2  = (const float*)d_in[16];
    float* out = (float*)d_out;

    void *p_q, *p_mu, *p_h, *p_x, *p_mumix, *p_ctx, *p_hm, *p_xm, *p_wH, *p_wL;
    cudaGetSymbolAddress(&p_q, g_q);
    cudaGetSymbolAddress(&p_mu, g_mu);
    cudaGetSymbolAddress(&p_h, g_h);
    cudaGetSymbolAddress(&p_x, g_x);
    cudaGetSymbolAddress(&p_mumix, g_mumix);
    cudaGetSymbolAddress(&p_ctx, g_ctx);
    cudaGetSymbolAddress(&p_hm, g_hm);
    cudaGetSymbolAddress(&p_xm, g_xm);
    cudaGetSymbolAddress(&p_wH, g_wH);
    cudaGetSymbolAddress(&p_wL, g_wL);

    edge_geom<<<(N_EDGES + 255) / 256, 256>>>(R, idx_i, idx_j, offs);
    build_table<<<NTAB, F3>>>(filt_W, filt_b);
    init_atoms<<<N_ATOMS, 128>>>(Z, emb);
    transpose_all<<<dim3(192, 15), 256>>>(int_W1, int_W2, mix_Wmu, mix_W1, mix_W2);
    build_rows<<<(N_ATOMS + 256) / 256, 256>>>(idx_i);

    const __nv_bfloat16* wH = (const __nv_bfloat16*)p_wH;
    const __nv_bfloat16* wL = (const __nv_bfloat16*)p_wL;

    auto gemm = [&](const float* A, size_t woff, const float* bias, float* C,
                    int M, int N, int K, int act) {
        mma_gemm<<<dim3(N / 64, (M + 127) / 128), 256>>>(
            A, wH + woff, wL + woff, bias, C, M, N, K, act);
    };

    for (int it = 0; it < 3; ++it) {
        size_t wb = (size_t)it * WT_PER_ITER;
        gemm((const float*)p_q, wb + 0,
             int_b1 + (long)it * F_DIM, (float*)p_h, N_ATOMS, F_DIM, F_DIM, 1);
        gemm((const float*)p_h, wb + 16384,
             int_b2 + (long)it * F3, (float*)p_x, N_ATOMS, F3, F_DIM, 0);

        edge_message_csr<<<N_ATOMS, 128>>>(idx_j);
        apply_mu<<<N_ATOMS, 128>>>();

        gemm((const float*)p_mu, wb + 65536,
             nullptr, (float*)p_mumix, 3 * N_ATOMS, 2 * F_DIM, F_DIM, 0);
        ctx_kernel<<<N_ATOMS, 128>>>();
        gemm((const float*)p_ctx, wb + 98304,
             mix_b1 + (long)it * F_DIM, (float*)p_hm, N_ATOMS, F_DIM, 2 * F_DIM, 1);
        gemm((const float*)p_hm, wb + 131072,
             mix_b2 + (long)it * F3, (float*)p_xm, N_ATOMS, F3, F_DIM, 0);
        mix_update<<<N_ATOMS, 128>>>();
    }

    cudaMemcpyAsync(out, p_q, (size_t)N_ATOMS * F_DIM * sizeof(float),
                    cudaMemcpyDeviceToDevice);
    cudaMemcpyAsync(out + (size_t)N_ATOMS * F_DIM, p_mu,
                    (size_t)N_ATOMS * 3 * F_DIM * sizeof(float),
                    cudaMemcpyDeviceToDevice);
}